// round 8
// baseline (speedup 1.0000x reference)
#include <cuda_runtime.h>
#include <math.h>

// Problem constants
#define Bn 256
#define Tn 512
#define En 128
#define Hn 256

typedef unsigned long long ull;

// ---------------- device scratch (static; no runtime allocation) ----------------
__device__ float g_xp[2 * Tn * Bn * 768];      // [dir][t][sb][768] fp32 (805 MB)
__device__ float g_h[2 * 2 * Hn * Bn];         // [parity][dir][k(=j)][sb]  (transposed)
__device__ float g_hfinal[2 * Bn * Hn];        // [dir][sb][j]
__device__ int   g_perm[Bn];                   // sorted pos -> original batch idx
__device__ int   g_slen[Bn];                   // lens sorted descending
__device__ unsigned g_bar;                     // global barrier counter

// ---------------- helpers ----------------
__device__ __forceinline__ void fma2(ull &a, ull x, ull y) {
    asm("fma.rn.f32x2 %0, %1, %2, %0;" : "+l"(a) : "l"(x), "l"(y));
}
__device__ __forceinline__ float f2lo(ull v) { return __uint_as_float((unsigned)(v & 0xffffffffull)); }
__device__ __forceinline__ float f2hi(ull v) { return __uint_as_float((unsigned)(v >> 32)); }
__device__ __forceinline__ ull packdup(float w) {
    unsigned u = __float_as_uint(w);
    return ((ull)u << 32) | (ull)u;
}
__device__ __forceinline__ float sigmf(float x) {
    float e = __expf(-fabsf(x));
    float s = __fdividef(1.f, 1.f + e);
    return (x >= 0.f) ? s : 1.f - s;
}
__device__ __forceinline__ float tanhf_fast(float x) {
    float e = __expf(-2.f * fabsf(x));
    float th = __fdividef(1.f - e, 1.f + e);
    return (x >= 0.f) ? th : -th;
}

// ---------------- prep: sort batches by len desc, zero h parity0, reset barrier ----
__global__ void prep_kernel(const int* __restrict__ lens) {
    __shared__ int sl[Bn];
    int i = threadIdx.x;
    sl[i] = lens[i];
    __syncthreads();
    int li = sl[i];
    int rank = 0;
    #pragma unroll 8
    for (int j = 0; j < Bn; j++) {
        int lj = sl[j];
        rank += (lj > li) || (lj == li && j < i);
    }
    g_perm[rank] = i;
    g_slen[rank] = li;
    if (i == 0) g_bar = 0u;
    // zero parity-0 h buffer: first 2*Hn*Bn floats
    for (int f = i; f < 2 * Hn * Bn; f += Bn) g_h[f] = 0.f;
}

// ---------------- phase 1: xp[d][t][sb][g] = x @ W_ih^T + b_ih --------------------
// grid: x = d*8 + tchunk (16), y = sb (256). 256 threads. dyn smem = 2*128*65*4 = 66560 B.
#define XPAD 65
__global__ __launch_bounds__(256) void xp_kernel(
    const int* __restrict__ seqs, const int* __restrict__ lens,
    const float* __restrict__ embed,
    const float* __restrict__ Wf, const float* __restrict__ Wb,
    const float* __restrict__ bf, const float* __restrict__ bb)
{
    extern __shared__ float sm[];
    float* x_s = sm;                 // [k=128][t=64] stride XPAD
    float* w_s = sm + 128 * XPAD;    // [k=128][g=64] stride XPAD

    int d = blockIdx.x >> 3;
    int chunk = blockIdx.x & 7;
    int sb = blockIdx.y;
    int b = g_perm[sb];
    int len = lens[b];
    int t0 = chunk * 64;
    if (t0 >= len) return;           // uniform per block

    const float* W = d ? Wb : Wf;
    const float* bi = d ? bb : bf;
    int tid = threadIdx.x;

    // stage embeddings for 64 tokens (transposed, padded)
    for (int f = tid; f < 64 * 128; f += 256) {
        int tt = f >> 7, k = f & 127;
        int t = t0 + tt;
        int pos = d ? max(len - 1 - t, 0) : t;
        int tok = seqs[b * Tn + pos];
        x_s[k * XPAD + tt] = embed[tok * En + k];
    }

    int tx = tid & 15;   // token group (4 tokens)
    int ty = tid >> 4;   // gate group (4 gates)

    for (int gt = 0; gt < 12; gt++) {     // 12 * 64 = 768 = 3H gate columns
        __syncthreads();
        for (int f = tid; f < 64 * 128; f += 256) {
            int g = f >> 7, k = f & 127;
            w_s[k * XPAD + g] = W[(gt * 64 + g) * En + k];
        }
        __syncthreads();

        float acc[4][4];
        #pragma unroll
        for (int i = 0; i < 4; i++)
            #pragma unroll
            for (int jj = 0; jj < 4; jj++) acc[i][jj] = 0.f;

        #pragma unroll 4
        for (int k = 0; k < 128; k++) {
            float xv[4], wv[4];
            #pragma unroll
            for (int i = 0; i < 4; i++) xv[i] = x_s[k * XPAD + tx * 4 + i];
            #pragma unroll
            for (int jj = 0; jj < 4; jj++) wv[jj] = w_s[k * XPAD + ty * 4 + jj];
            #pragma unroll
            for (int i = 0; i < 4; i++)
                #pragma unroll
                for (int jj = 0; jj < 4; jj++)
                    acc[i][jj] = fmaf(xv[i], wv[jj], acc[i][jj]);
        }

        float4 b4 = *(const float4*)&bi[gt * 64 + ty * 4];
        #pragma unroll
        for (int i = 0; i < 4; i++) {
            int t = t0 + tx * 4 + i;
            float4 o;
            o.x = acc[i][0] + b4.x; o.y = acc[i][1] + b4.y;
            o.z = acc[i][2] + b4.z; o.w = acc[i][3] + b4.w;
            *(float4*)&g_xp[((d * Tn + t) * Bn + sb) * 768 + gt * 64 + ty * 4] = o;
        }
    }
}

// ---------------- phase 2: persistent recurrence, 128 CTAs x 128 threads ----------
// CTA = (dir, sb-tile of 64, j-tile of 16). One global barrier per step.
#define HPAD 66
#define WPAD 49
#define REC_SMEM (Hn * HPAD * 4 + Hn * WPAD * 8)   // 67584 + 100352 = 167936 B

__global__ __launch_bounds__(128, 1) void rec_kernel(
    const float* __restrict__ Whf, const float* __restrict__ Whb,
    const float* __restrict__ bhf, const float* __restrict__ bhb)
{
    extern __shared__ char dsm[];
    float* h_s = (float*)dsm;                         // [k=256][b=64] stride HPAD
    ull* w2_s = (ull*)(dsm + Hn * HPAD * 4);          // [k=256][row=48] stride WPAD, (w,w) pairs
    __shared__ int slen_s[64];
    __shared__ float bhh_s[48];
    __shared__ int s_tmax;

    int tid = threadIdx.x;
    int cta = blockIdx.x;
    int d = cta >> 6;
    int rem = cta & 63;
    int sb0 = (rem >> 4) * 64;
    int j0 = (rem & 15) * 16;
    const float* Whh = d ? Whb : Whf;
    const float* bhh = d ? bhb : bhf;

    // stage weights (once): rows {g*256 + j0 + jl}, duplicated into f32x2
    for (int f = tid; f < 48 * 256; f += 128) {
        int r = f >> 8, k = f & 255;
        float w = Whh[((r >> 4) * Hn + j0 + (r & 15)) * Hn + k];
        w2_s[k * WPAD + r] = packdup(w);
    }
    if (tid < 48) bhh_s[tid] = bhh[(tid >> 4) * Hn + j0 + (tid & 15)];
    if (tid < 64) slen_s[tid] = g_slen[sb0 + tid];
    if (tid == 0) s_tmax = g_slen[0];
    __syncthreads();

    int tmax = s_tmax;
    int jl = tid & 15;
    int bgrp = tid >> 4;       // 0..7, each owns 8 consecutive b
    int jg = j0 + jl;
    float bh0 = bhh_s[jl], bh1 = bhh_s[16 + jl], bh2 = bhh_s[32 + jl];
    int na = 64;
    unsigned target = 0;

    for (int t = 0; t < tmax; t++) {
        int par = t & 1, npar = par ^ 1;
        while (na > 0 && slen_s[na - 1] <= t) --na;

        if (na > 0) {
            // stage previous h (transposed global layout -> conflict-free STS)
            const float* hsrc = g_h + (par * 2 + d) * (Hn * Bn);
            for (int f = tid; f < Hn * 64; f += 128) {
                int k = f >> 6, bb = f & 63;
                if (bb < na) h_s[k * HPAD + bb] = __ldcg(hsrc + k * Bn + sb0 + bb);
            }
            __syncthreads();

            if (slen_s[bgrp * 8] > t) {
                ull a[12];
                #pragma unroll
                for (int q = 0; q < 12; q++) a[q] = 0ull;

                const float* hrow = h_s + bgrp * 8;
                const ull* wrow = w2_s + jl;
                #pragma unroll 4
                for (int k = 0; k < Hn; k++) {
                    const ull* hv = (const ull*)(hrow + k * HPAD);
                    ull h0 = hv[0], h1 = hv[1], h2v = hv[2], h3 = hv[3];
                    const ull* wk = wrow + k * WPAD;
                    ull w0 = wk[0], w1 = wk[16], w2w = wk[32];
                    fma2(a[0], h0, w0);  fma2(a[1], h1, w0);
                    fma2(a[2], h2v, w0); fma2(a[3], h3, w0);
                    fma2(a[4], h0, w1);  fma2(a[5], h1, w1);
                    fma2(a[6], h2v, w1); fma2(a[7], h3, w1);
                    fma2(a[8], h0, w2w); fma2(a[9], h1, w2w);
                    fma2(a[10], h2v, w2w); fma2(a[11], h3, w2w);
                }

                // epilogue: gates + h update for the 8 owned rows
                #pragma unroll
                for (int q = 0; q < 4; q++) {
                    #pragma unroll
                    for (int s = 0; s < 2; s++) {
                        int bl = bgrp * 8 + q * 2 + s;
                        int L = slen_s[bl];
                        if (L > t) {
                            float hpr = s ? f2hi(a[q])     : f2lo(a[q]);
                            float hpz = s ? f2hi(a[4 + q]) : f2lo(a[4 + q]);
                            float hpn = s ? f2hi(a[8 + q]) : f2lo(a[8 + q]);
                            int xo = ((d * Tn + t) * Bn + sb0 + bl) * 768 + jg;
                            float xr = __ldg(&g_xp[xo]);
                            float xz = __ldg(&g_xp[xo + 256]);
                            float xn = __ldg(&g_xp[xo + 512]);
                            float r = sigmf(xr + hpr + bh0);
                            float z = sigmf(xz + hpz + bh1);
                            float n = tanhf_fast(xn + r * (hpn + bh2));
                            float hold = h_s[jg * HPAD + bl];
                            float hnew = (1.f - z) * n + z * hold;
                            g_h[(npar * 2 + d) * (Hn * Bn) + jg * Bn + sb0 + bl] = hnew;
                            if (L == t + 1)
                                g_hfinal[(d * Bn + sb0 + bl) * Hn + jg] = hnew;
                        }
                    }
                }
            }
        }

        // ---- grid barrier (all 128 CTAs, every step) ----
        __threadfence();
        __syncthreads();
        target += 128;
        if (tid == 0) {
            atomicAdd(&g_bar, 1u);
            volatile unsigned* vb = &g_bar;
            while (*vb < target) { }
        }
        __syncthreads();
    }
}

// ---------------- phase 3: FC head: out[b][c] = [h_f | h_b] @ W_fc^T + b_fc -------
__global__ void fc_kernel(const float* __restrict__ Wfc, const float* __restrict__ bfc,
                          float* __restrict__ out)
{
    int sb = blockIdx.x;
    int b = g_perm[sb];
    int tid = threadIdx.x;   // 128
    float a0 = 0.f, a1 = 0.f;
    for (int j = tid; j < Hn; j += 128) {
        float hf = g_hfinal[(0 * Bn + sb) * Hn + j];
        float hb = g_hfinal[(1 * Bn + sb) * Hn + j];
        a0 += hf * Wfc[j]       + hb * Wfc[256 + j];
        a1 += hf * Wfc[512 + j] + hb * Wfc[768 + j];
    }
    #pragma unroll
    for (int off = 16; off; off >>= 1) {
        a0 += __shfl_down_sync(0xffffffffu, a0, off);
        a1 += __shfl_down_sync(0xffffffffu, a1, off);
    }
    __shared__ float r0[4], r1[4];
    int wid = tid >> 5, lane = tid & 31;
    if (lane == 0) { r0[wid] = a0; r1[wid] = a1; }
    __syncthreads();
    if (tid == 0) {
        out[b * 2 + 0] = r0[0] + r0[1] + r0[2] + r0[3] + bfc[0];
        out[b * 2 + 1] = r1[0] + r1[1] + r1[2] + r1[3] + bfc[1];
    }
}

// ---------------- launch ----------------
extern "C" void kernel_launch(void* const* d_in, const int* in_sizes, int n_in,
                              void* d_out, int out_size)
{
    const int*   seqs  = (const int*)d_in[0];
    const int*   lens  = (const int*)d_in[1];
    const float* embed = (const float*)d_in[2];
    const float* Wih_f = (const float*)d_in[3];
    const float* Whh_f = (const float*)d_in[4];
    const float* bih_f = (const float*)d_in[5];
    const float* bhh_f = (const float*)d_in[6];
    const float* Wih_b = (const float*)d_in[7];
    const float* Whh_b = (const float*)d_in[8];
    const float* bih_b = (const float*)d_in[9];
    const float* bhh_b = (const float*)d_in[10];
    const float* Wfc   = (const float*)d_in[11];
    const float* bfc   = (const float*)d_in[12];
    float* out = (float*)d_out;

    const int xp_smem = 2 * 128 * XPAD * 4;   // 66560
    cudaFuncSetAttribute(xp_kernel, cudaFuncAttributeMaxDynamicSharedMemorySize, xp_smem);
    cudaFuncSetAttribute(rec_kernel, cudaFuncAttributeMaxDynamicSharedMemorySize, REC_SMEM);

    prep_kernel<<<1, 256>>>(lens);
    xp_kernel<<<dim3(16, 256), 256, xp_smem>>>(seqs, lens, embed,
                                               Wih_f, Wih_b, bih_f, bih_b);
    rec_kernel<<<128, 128, REC_SMEM>>>(Whh_f, Whh_b, bhh_f, bhh_b);
    fc_kernel<<<256, 128>>>(Wfc, bfc, out);
}

// round 10
// speedup vs baseline: 2.1166x; 2.1166x over previous
#include <cuda_runtime.h>
#include <math.h>

// Problem constants
#define Bn 256
#define Tn 512
#define En 128
#define Hn 256

typedef unsigned long long ull;

// ---------------- device scratch (static; no runtime allocation) ----------------
__device__ __align__(16) float g_xp[2 * Tn * Bn * 768];   // [dir][t][sb][768] fp32
__device__ __align__(16) float g_h[2 * 2 * Hn * Bn];      // [parity][dir][k(=j)][sb]
__device__ __align__(16) float g_hfinal[2 * Bn * Hn];     // [dir][sb][j]
__device__ int   g_perm[Bn];                  // sorted pos -> original batch idx
__device__ int   g_slen[Bn];                  // lens sorted descending
__device__ unsigned g_bar;                    // global barrier counter

// ---------------- helpers ----------------
__device__ __forceinline__ void fma2(ull &a, ull x, ull y) {
    asm("fma.rn.f32x2 %0, %1, %2, %0;" : "+l"(a) : "l"(x), "l"(y));
}
__device__ __forceinline__ float f2lo(ull v) { return __uint_as_float((unsigned)(v & 0xffffffffull)); }
__device__ __forceinline__ float f2hi(ull v) { return __uint_as_float((unsigned)(v >> 32)); }
__device__ __forceinline__ ull pk(unsigned lo, unsigned hi) { return ((ull)hi << 32) | (ull)lo; }
__device__ __forceinline__ ull packdup(float w) {
    unsigned u = __float_as_uint(w);
    return ((ull)u << 32) | (ull)u;
}
__device__ __forceinline__ float sigmf(float x) {
    float e = __expf(-fabsf(x));
    float s = __fdividef(1.f, 1.f + e);
    return (x >= 0.f) ? s : 1.f - s;
}
__device__ __forceinline__ float tanhf_fast(float x) {
    float e = __expf(-2.f * fabsf(x));
    float th = __fdividef(1.f - e, 1.f + e);
    return (x >= 0.f) ? th : -th;
}

// ---------------- prep: sort batches by len desc, zero h parity0, reset barrier ----
__global__ void prep_kernel(const int* __restrict__ lens) {
    __shared__ int sl[Bn];
    int i = threadIdx.x;
    sl[i] = lens[i];
    __syncthreads();
    int li = sl[i];
    int rank = 0;
    #pragma unroll 8
    for (int j = 0; j < Bn; j++) {
        int lj = sl[j];
        rank += (lj > li) || (lj == li && j < i);
    }
    g_perm[rank] = i;
    g_slen[rank] = li;
    if (i == 0) g_bar = 0u;
    for (int f = i; f < 2 * Hn * Bn; f += Bn) g_h[f] = 0.f;
}

// ---------------- dummy: aligns rec_kernel onto the profiler's capture slot ------
__global__ void dummy_kernel() {}

// ---------------- phase 1: xp[d][t][sb][g] = x @ W_ih^T + b_ih --------------------
#define XPAD 65
__global__ __launch_bounds__(256) void xp_kernel(
    const int* __restrict__ seqs, const int* __restrict__ lens,
    const float* __restrict__ embed,
    const float* __restrict__ Wf, const float* __restrict__ Wb,
    const float* __restrict__ bf, const float* __restrict__ bb)
{
    extern __shared__ float sm[];
    float* x_s = sm;                 // [k=128][t=64] stride XPAD
    float* w_s = sm + 128 * XPAD;    // [k=128][g=64] stride XPAD

    int d = blockIdx.x >> 3;
    int chunk = blockIdx.x & 7;
    int sb = blockIdx.y;
    int b = g_perm[sb];
    int len = lens[b];
    int t0 = chunk * 64;
    if (t0 >= len) return;

    const float* W = d ? Wb : Wf;
    const float* bi = d ? bb : bf;
    int tid = threadIdx.x;

    for (int f = tid; f < 64 * 128; f += 256) {
        int tt = f >> 7, k = f & 127;
        int t = t0 + tt;
        int pos = d ? max(len - 1 - t, 0) : t;
        int tok = seqs[b * Tn + pos];
        x_s[k * XPAD + tt] = embed[tok * En + k];
    }

    int tx = tid & 15;
    int ty = tid >> 4;

    for (int gt = 0; gt < 12; gt++) {     // 12 * 64 = 768 = 3H
        __syncthreads();
        for (int f = tid; f < 64 * 128; f += 256) {
            int g = f >> 7, k = f & 127;
            w_s[k * XPAD + g] = W[(gt * 64 + g) * En + k];
        }
        __syncthreads();

        float acc[4][4];
        #pragma unroll
        for (int i = 0; i < 4; i++)
            #pragma unroll
            for (int jj = 0; jj < 4; jj++) acc[i][jj] = 0.f;

        #pragma unroll 4
        for (int k = 0; k < 128; k++) {
            float xv[4], wv[4];
            #pragma unroll
            for (int i = 0; i < 4; i++) xv[i] = x_s[k * XPAD + tx * 4 + i];
            #pragma unroll
            for (int jj = 0; jj < 4; jj++) wv[jj] = w_s[k * XPAD + ty * 4 + jj];
            #pragma unroll
            for (int i = 0; i < 4; i++)
                #pragma unroll
                for (int jj = 0; jj < 4; jj++)
                    acc[i][jj] = fmaf(xv[i], wv[jj], acc[i][jj]);
        }

        float4 b4 = *(const float4*)&bi[gt * 64 + ty * 4];
        #pragma unroll
        for (int i = 0; i < 4; i++) {
            int t = t0 + tx * 4 + i;
            float4 o;
            o.x = acc[i][0] + b4.x; o.y = acc[i][1] + b4.y;
            o.z = acc[i][2] + b4.z; o.w = acc[i][3] + b4.w;
            *(float4*)&g_xp[((d * Tn + t) * Bn + sb) * 768 + gt * 64 + ty * 4] = o;
        }
    }
}

// ---------------- phase 2: persistent recurrence, 128 CTAs x 256 threads ----------
// CTA = (dir, sb-tile of 64, j-tile of 16). Thread = (jl 0..15, bq 0..15 of 4 b).
// h_s: [k=256][b=64] fp32 (64 KB). w2_s: [k2=128][row=48][kpar=2] dup-f32x2 (96 KB).
// Grid barrier counts only ACTIVE CTAs per step (tile i active iff m_i > t);
// finished CTAs return WITHOUT crediting (no pre-credit -> no early release).
#define REC_SMEM (Hn * 64 * 4 + (Hn / 2) * 48 * 2 * 8)   // 65536 + 98304 = 163840

__global__ __launch_bounds__(256, 1) void rec_kernel(
    const float* __restrict__ Whf, const float* __restrict__ Whb,
    const float* __restrict__ bhf, const float* __restrict__ bhb)
{
    extern __shared__ char dsm[];
    float* h_s = (float*)dsm;                        // [k][b] stride 64
    ull* w2_s = (ull*)(dsm + Hn * 64 * 4);           // [k2][48][2]
    __shared__ int slen_s[64];
    __shared__ float bhh_s[48];
    __shared__ int m_s[4];                           // per-tile max lens

    int tid = threadIdx.x;
    int cta = blockIdx.x;
    int d = cta >> 6;
    int rem = cta & 63;
    int sb0 = (rem >> 4) * 64;
    int j0 = (rem & 15) * 16;
    const float* Whh = d ? Whb : Whf;
    const float* bhh = d ? bhb : bhf;

    // stage weights once: row r = g*16+jl -> Whh[(g*256 + j0 + jl)][k], k-paired dup
    for (int f = tid; f < 48 * 256; f += 256) {
        int r = f >> 8, k = f & 255;
        float w = Whh[((r >> 4) * Hn + j0 + (r & 15)) * Hn + k];
        w2_s[(k >> 1) * 96 + r * 2 + (k & 1)] = packdup(w);
    }
    if (tid < 48) bhh_s[tid] = bhh[(tid >> 4) * Hn + j0 + (tid & 15)];
    if (tid < 64) slen_s[tid] = g_slen[sb0 + tid];
    if (tid < 4)  m_s[tid] = g_slen[tid * 64];       // sorted desc -> first is tile max
    __syncthreads();

    int tmax = m_s[0];
    int jl = tid & 15;
    int bq = tid >> 4;            // 0..15, each owns 4 consecutive b
    int jg = j0 + jl;
    float bh0 = bhh_s[jl], bh1 = bhh_s[16 + jl], bh2 = bhh_s[32 + jl];
    int myM = slen_s[0];          // this CTA's tile max
    unsigned target = 0;
    int wb0 = (tid >> 5) * 8;     // first (longest) b of this warp's 8-batch span

    for (int t = 0; t < tmax; t++) {
        if (myM <= t) return;     // finished: no work, no arrival, others don't count us

        int par = t & 1, npar = par ^ 1;

        // ---- stage previous h (vectorized, conflict-free) ----
        {
            const float* hsrc = g_h + (par * 2 + d) * (Hn * Bn) + sb0;
            #pragma unroll
            for (int i = 0; i < 16; i++) {
                int f = tid + i * 256;            // 0..4095 float4 slots
                int k = f >> 4, b4 = f & 15;
                float4 v = __ldcg((const float4*)(hsrc + k * Bn) + b4);
                *(float4*)(h_s + k * 64 + b4 * 4) = v;
            }
        }
        __syncthreads();

        if (slen_s[wb0] > t) {    // warp-uniform active check
            // prefetch xp operands (independent of h) so DRAM latency hides under k-loop
            float xr[4], xz[4], xn[4];
            #pragma unroll
            for (int p = 0; p < 4; p++) {
                int bl = bq * 4 + p;
                bool act = slen_s[bl] > t;
                int xo = ((d * Tn + t) * Bn + sb0 + bl) * 768 + jg;
                xr[p] = act ? __ldg(&g_xp[xo])       : 0.f;
                xz[p] = act ? __ldg(&g_xp[xo + 256]) : 0.f;
                xn[p] = act ? __ldg(&g_xp[xo + 512]) : 0.f;
            }

            ull a0 = 0, a1 = 0, a2 = 0, a3 = 0, a4 = 0, a5 = 0;  // [r,z,n] x [b01,b23]
            const char* wbase = (const char*)(w2_s + jl * 2);
            const float* hbase = h_s + bq * 4;
            #pragma unroll 2
            for (int k2 = 0; k2 < 128; k2++) {
                uint4 ua = *(const uint4*)(hbase + (k2 * 2) * 64);
                uint4 ub = *(const uint4*)(hbase + (k2 * 2 + 1) * 64);
                ull ha01 = pk(ua.x, ua.y), ha23 = pk(ua.z, ua.w);
                ull hb01 = pk(ub.x, ub.y), hb23 = pk(ub.z, ub.w);
                const ull* wk = (const ull*)(wbase + k2 * 768);   // 96 ull * 8B
                ulonglong2 wr = *(const ulonglong2*)(wk);
                ulonglong2 wz = *(const ulonglong2*)(wk + 32);
                ulonglong2 wn = *(const ulonglong2*)(wk + 64);
                fma2(a0, ha01, wr.x); fma2(a1, ha23, wr.x);
                fma2(a2, ha01, wz.x); fma2(a3, ha23, wz.x);
                fma2(a4, ha01, wn.x); fma2(a5, ha23, wn.x);
                fma2(a0, hb01, wr.y); fma2(a1, hb23, wr.y);
                fma2(a2, hb01, wz.y); fma2(a3, hb23, wz.y);
                fma2(a4, hb01, wn.y); fma2(a5, hb23, wn.y);
            }

            // epilogue: gates + h update for the 4 owned rows
            float hpr[4] = { f2lo(a0), f2hi(a0), f2lo(a1), f2hi(a1) };
            float hpz[4] = { f2lo(a2), f2hi(a2), f2lo(a3), f2hi(a3) };
            float hpn[4] = { f2lo(a4), f2hi(a4), f2lo(a5), f2hi(a5) };
            #pragma unroll
            for (int p = 0; p < 4; p++) {
                int bl = bq * 4 + p;
                int L = slen_s[bl];
                if (L > t) {
                    float r = sigmf(xr[p] + hpr[p] + bh0);
                    float z = sigmf(xz[p] + hpz[p] + bh1);
                    float n = tanhf_fast(xn[p] + r * (hpn[p] + bh2));
                    float hold = h_s[jg * 64 + bl];
                    float hnew = (1.f - z) * n + z * hold;
                    g_h[(npar * 2 + d) * (Hn * Bn) + jg * Bn + sb0 + bl] = hnew;
                    if (L == t + 1)
                        g_hfinal[(d * Bn + sb0 + bl) * Hn + jg] = hnew;
                }
            }
        }

        // ---- grid barrier over ACTIVE CTAs only ----
        __threadfence();
        __syncthreads();
        if (tid == 0) {
            int act = 0;
            #pragma unroll
            for (int i = 0; i < 4; i++) act += (m_s[i] > t) ? 32 : 0;
            target += (unsigned)act;          // same value computed by every active CTA
            atomicAdd(&g_bar, 1u);
            volatile unsigned* vb = &g_bar;
            while (*vb < target) __nanosleep(32);
        }
        __syncthreads();
    }
}

// ---------------- phase 3: FC head ----------------
__global__ void fc_kernel(const float* __restrict__ Wfc, const float* __restrict__ bfc,
                          float* __restrict__ out)
{
    int sb = blockIdx.x;
    int b = g_perm[sb];
    int tid = threadIdx.x;   // 128
    float a0 = 0.f, a1 = 0.f;
    for (int j = tid; j < Hn; j += 128) {
        float hf = g_hfinal[(0 * Bn + sb) * Hn + j];
        float hb = g_hfinal[(1 * Bn + sb) * Hn + j];
        a0 += hf * Wfc[j]       + hb * Wfc[256 + j];
        a1 += hf * Wfc[512 + j] + hb * Wfc[768 + j];
    }
    #pragma unroll
    for (int off = 16; off; off >>= 1) {
        a0 += __shfl_down_sync(0xffffffffu, a0, off);
        a1 += __shfl_down_sync(0xffffffffu, a1, off);
    }
    __shared__ float r0[4], r1[4];
    int wid = tid >> 5, lane = tid & 31;
    if (lane == 0) { r0[wid] = a0; r1[wid] = a1; }
    __syncthreads();
    if (tid == 0) {
        out[b * 2 + 0] = r0[0] + r0[1] + r0[2] + r0[3] + bfc[0];
        out[b * 2 + 1] = r1[0] + r1[1] + r1[2] + r1[3] + bfc[1];
    }
}

// ---------------- launch ----------------
extern "C" void kernel_launch(void* const* d_in, const int* in_sizes, int n_in,
                              void* d_out, int out_size)
{
    const int*   seqs  = (const int*)d_in[0];
    const int*   lens  = (const int*)d_in[1];
    const float* embed = (const float*)d_in[2];
    const float* Wih_f = (const float*)d_in[3];
    const float* Whh_f = (const float*)d_in[4];
    const float* bih_f = (const float*)d_in[5];
    const float* bhh_f = (const float*)d_in[6];
    const float* Wih_b = (const float*)d_in[7];
    const float* Whh_b = (const float*)d_in[8];
    const float* bih_b = (const float*)d_in[9];
    const float* bhh_b = (const float*)d_in[10];
    const float* Wfc   = (const float*)d_in[11];
    const float* bfc   = (const float*)d_in[12];
    float* out = (float*)d_out;

    const int xp_smem = 2 * 128 * XPAD * 4;
    cudaFuncSetAttribute(xp_kernel, cudaFuncAttributeMaxDynamicSharedMemorySize, xp_smem);
    cudaFuncSetAttribute(rec_kernel, cudaFuncAttributeMaxDynamicSharedMemorySize, REC_SMEM);

    prep_kernel<<<1, 256>>>(lens);
    xp_kernel<<<dim3(16, 256), 256, xp_smem>>>(seqs, lens, embed,
                                               Wih_f, Wih_b, bih_f, bih_b);
    dummy_kernel<<<1, 32>>>();   // aligns rec_kernel onto ncu's -s 5 capture slot
    rec_kernel<<<128, 256, REC_SMEM>>>(Whh_f, Whh_b, bhh_f, bhh_b);
    fc_kernel<<<256, 128>>>(Wfc, bfc, out);
}

// round 11
// speedup vs baseline: 2.4991x; 1.1807x over previous
#include <cuda_runtime.h>
#include <math.h>

// Problem constants
#define Bn 256
#define Tn 512
#define En 128
#define Hn 256

typedef unsigned long long ull;

// ---------------- device scratch (static; no runtime allocation) ----------------
__device__ __align__(16) float g_xp[2 * Tn * Bn * 768];   // [dir][t][sb][768] fp32
__device__ __align__(16) ull   g_h2[2 * 2 * 128 * Bn];    // [par][dir][k2][bglob] (k-paired h)
__device__ __align__(16) float g_hfinal[2 * Bn * Hn];     // [dir][sb][j]
__device__ int   g_perm[Bn];                  // sorted pos -> original batch idx
__device__ int   g_slen[Bn];                  // lens sorted descending
__device__ unsigned g_bar;                    // global barrier counter

// ---------------- helpers ----------------
__device__ __forceinline__ void fma2(ull &a, ull x, ull y) {
    asm("fma.rn.f32x2 %0, %1, %2, %0;" : "+l"(a) : "l"(x), "l"(y));
}
__device__ __forceinline__ float f2lo(ull v) { return __uint_as_float((unsigned)(v & 0xffffffffull)); }
__device__ __forceinline__ float f2hi(ull v) { return __uint_as_float((unsigned)(v >> 32)); }
__device__ __forceinline__ ull pk(unsigned lo, unsigned hi) { return ((ull)hi << 32) | (ull)lo; }
__device__ __forceinline__ float sigmf(float x) {
    float e = __expf(-fabsf(x));
    float s = __fdividef(1.f, 1.f + e);
    return (x >= 0.f) ? s : 1.f - s;
}
__device__ __forceinline__ float tanhf_fast(float x) {
    float e = __expf(-2.f * fabsf(x));
    float th = __fdividef(1.f - e, 1.f + e);
    return (x >= 0.f) ? th : -th;
}

// ---------------- prep: sort batches by len desc, zero h2 parity0, reset barrier --
__global__ void prep_kernel(const int* __restrict__ lens) {
    __shared__ int sl[Bn];
    int i = threadIdx.x;
    sl[i] = lens[i];
    __syncthreads();
    int li = sl[i];
    int rank = 0;
    #pragma unroll 8
    for (int j = 0; j < Bn; j++) {
        int lj = sl[j];
        rank += (lj > li) || (lj == li && j < i);
    }
    g_perm[rank] = i;
    g_slen[rank] = li;
    if (i == 0) g_bar = 0u;
    // zero parity-0 h2 buffer: first 2*128*Bn ulls ([par=0][dir][k2][b])
    for (int f = i; f < 2 * 128 * Bn; f += Bn) g_h2[f] = 0ull;
}

// ---------------- dummy: aligns rec_kernel onto the profiler's capture slot ------
__global__ void dummy_kernel() {}

// ---------------- phase 1: xp[d][t][sb][g] = x @ W_ih^T + b_ih --------------------
#define XPAD 65
__global__ __launch_bounds__(256) void xp_kernel(
    const int* __restrict__ seqs, const int* __restrict__ lens,
    const float* __restrict__ embed,
    const float* __restrict__ Wf, const float* __restrict__ Wb,
    const float* __restrict__ bf, const float* __restrict__ bb)
{
    extern __shared__ float sm[];
    float* x_s = sm;                 // [k=128][t=64] stride XPAD
    float* w_s = sm + 128 * XPAD;    // [k=128][g=64] stride XPAD

    int d = blockIdx.x >> 3;
    int chunk = blockIdx.x & 7;
    int sb = blockIdx.y;
    int b = g_perm[sb];
    int len = lens[b];
    int t0 = chunk * 64;
    if (t0 >= len) return;

    const float* W = d ? Wb : Wf;
    const float* bi = d ? bb : bf;
    int tid = threadIdx.x;

    for (int f = tid; f < 64 * 128; f += 256) {
        int tt = f >> 7, k = f & 127;
        int t = t0 + tt;
        int pos = d ? max(len - 1 - t, 0) : t;
        int tok = seqs[b * Tn + pos];
        x_s[k * XPAD + tt] = embed[tok * En + k];
    }

    int tx = tid & 15;
    int ty = tid >> 4;

    for (int gt = 0; gt < 12; gt++) {     // 12 * 64 = 768 = 3H
        __syncthreads();
        for (int f = tid; f < 64 * 128; f += 256) {
            int g = f >> 7, k = f & 127;
            w_s[k * XPAD + g] = W[(gt * 64 + g) * En + k];
        }
        __syncthreads();

        float acc[4][4];
        #pragma unroll
        for (int i = 0; i < 4; i++)
            #pragma unroll
            for (int jj = 0; jj < 4; jj++) acc[i][jj] = 0.f;

        #pragma unroll 4
        for (int k = 0; k < 128; k++) {
            float xv[4], wv[4];
            #pragma unroll
            for (int i = 0; i < 4; i++) xv[i] = x_s[k * XPAD + tx * 4 + i];
            #pragma unroll
            for (int jj = 0; jj < 4; jj++) wv[jj] = w_s[k * XPAD + ty * 4 + jj];
            #pragma unroll
            for (int i = 0; i < 4; i++)
                #pragma unroll
                for (int jj = 0; jj < 4; jj++)
                    acc[i][jj] = fmaf(xv[i], wv[jj], acc[i][jj]);
        }

        float4 b4 = *(const float4*)&bi[gt * 64 + ty * 4];
        #pragma unroll
        for (int i = 0; i < 4; i++) {
            int t = t0 + tx * 4 + i;
            float4 o;
            o.x = acc[i][0] + b4.x; o.y = acc[i][1] + b4.y;
            o.z = acc[i][2] + b4.z; o.w = acc[i][3] + b4.w;
            *(float4*)&g_xp[((d * Tn + t) * Bn + sb) * 768 + gt * 64 + ty * 4] = o;
        }
    }
}

// ---------------- phase 2: persistent recurrence, 128 CTAs x 256 threads ----------
// CTA = (dir, sb-tile 64, j-tile 16). Lane map: jl = (w&1)*8 + (lane&7),
// bq = (w>>1)*4 + (lane>>3); each thread owns 4 batches, 3 gate rows.
// f32x2 packs k-parity (even,odd) partials: NO weight duplication.
// smem: h2_s [k2=128][b=64] ull (64KB); wrz_s [k2][jl=16] ulonglong2 (32KB);
//       wn_s [k2][jl] ull (16KB). Total 112KB.
#define REC_SMEM (128 * 64 * 8 + 128 * 16 * 16 + 128 * 16 * 8)   // 114688

__global__ __launch_bounds__(256, 1) void rec_kernel(
    const float* __restrict__ Whf, const float* __restrict__ Whb,
    const float* __restrict__ bhf, const float* __restrict__ bhb)
{
    extern __shared__ char dsm[];
    ull* h2_s = (ull*)dsm;                                  // [k2][64]
    ulonglong2* wrz_s = (ulonglong2*)(dsm + 65536);         // [k2][16]
    ull* wn_s = (ull*)(dsm + 65536 + 32768);                // [k2][16]
    __shared__ int slen_s[64];
    __shared__ float bhh_s[48];
    __shared__ int m_s[4];                                  // per-tile max lens

    int tid = threadIdx.x;
    int lane = tid & 31, w = tid >> 5;
    int cta = blockIdx.x;
    int d = cta >> 6;
    int rem = cta & 63;
    int sb0 = (rem >> 4) * 64;
    int j0 = (rem & 15) * 16;
    const float* Whh = d ? Whb : Whf;
    const float* bhh = d ? bhb : bhf;

    // stage weights once: k-paired (w_2k2, w_2k2+1), gates packed per (k2, jl)
    for (int idx = tid; idx < 2048; idx += 256) {
        int jl_ = idx & 15, k2 = idx >> 4;
        ull wr = *(const ull*)&Whh[(j0 + jl_) * Hn + 2 * k2];
        ull wz = *(const ull*)&Whh[(Hn + j0 + jl_) * Hn + 2 * k2];
        ull wn = *(const ull*)&Whh[(2 * Hn + j0 + jl_) * Hn + 2 * k2];
        wrz_s[k2 * 16 + jl_] = make_ulonglong2(wr, wz);
        wn_s[k2 * 16 + jl_] = wn;
    }
    if (tid < 48) bhh_s[tid] = bhh[(tid >> 4) * Hn + j0 + (tid & 15)];
    if (tid < 64) slen_s[tid] = g_slen[sb0 + tid];
    if (tid < 4)  m_s[tid] = g_slen[tid * 64];
    __syncthreads();

    int tmax = m_s[0];
    int jl = (w & 1) * 8 + (lane & 7);
    int bq = (w >> 1) * 4 + (lane >> 3);
    int jg = j0 + jl;
    float bh0 = bhh_s[jl], bh1 = bhh_s[16 + jl], bh2 = bhh_s[32 + jl];
    int myM = slen_s[0];
    int wb0 = (w >> 1) * 16;      // longest batch of this warp's 16-batch span
    unsigned target = 0;

    for (int t = 0; t < tmax; t++) {
        if (myM <= t) return;     // finished: no arrival; barrier counts only active CTAs

        int par = t & 1, npar = par ^ 1;

        // ---- stage previous h2 (coalesced ull copy, conflict-free STS) ----
        {
            const ull* hsrc = g_h2 + (size_t)((par * 2 + d) * 128) * Bn + sb0;
            #pragma unroll
            for (int i = 0; i < 16; i++) {
                int f = tid + i * 256;            // 0..4095 16B chunks
                int k2 = f >> 5, bp = f & 31;
                uint4 v = __ldcg((const uint4*)(hsrc + k2 * Bn) + bp);
                *(uint4*)(h2_s + k2 * 64 + bp * 2) = v;
            }
        }
        __syncthreads();

        if (slen_s[wb0] > t) {    // warp-uniform active check
            // prefetch xp operands (h-independent; DRAM latency hides under k-loop)
            float xr[4], xz[4], xn[4];
            #pragma unroll
            for (int p = 0; p < 4; p++) {
                int bl = bq * 4 + p;
                bool act = slen_s[bl] > t;
                const float* xo = g_xp + ((size_t)(d * Tn + t) * Bn + sb0 + bl) * 768 + jg;
                xr[p] = act ? __ldg(xo)       : 0.f;
                xz[p] = act ? __ldg(xo + 256) : 0.f;
                xn[p] = act ? __ldg(xo + 512) : 0.f;
            }

            ull ar0=0,ar1=0,ar2=0,ar3=0, az0=0,az1=0,az2=0,az3=0, an0=0,an1=0,an2=0,an3=0;
            const ull* hbase = h2_s + bq * 4;
            const ulonglong2* wrzb = wrz_s + jl;
            const ull* wnb = wn_s + jl;
            #pragma unroll 4
            for (int k2 = 0; k2 < 128; k2++) {
                ulonglong2 ha = *(const ulonglong2*)(hbase + k2 * 64);      // b0,b1
                ulonglong2 hb = *(const ulonglong2*)(hbase + k2 * 64 + 2);  // b2,b3
                ulonglong2 wrz = wrzb[k2 * 16];
                ull wn = wnb[k2 * 16];
                fma2(ar0, ha.x, wrz.x); fma2(ar1, ha.y, wrz.x);
                fma2(ar2, hb.x, wrz.x); fma2(ar3, hb.y, wrz.x);
                fma2(az0, ha.x, wrz.y); fma2(az1, ha.y, wrz.y);
                fma2(az2, hb.x, wrz.y); fma2(az3, hb.y, wrz.y);
                fma2(an0, ha.x, wn);    fma2(an1, ha.y, wn);
                fma2(an2, hb.x, wn);    fma2(an3, hb.y, wn);
            }

            float hpr[4] = { f2lo(ar0)+f2hi(ar0), f2lo(ar1)+f2hi(ar1),
                             f2lo(ar2)+f2hi(ar2), f2lo(ar3)+f2hi(ar3) };
            float hpz[4] = { f2lo(az0)+f2hi(az0), f2lo(az1)+f2hi(az1),
                             f2lo(az2)+f2hi(az2), f2lo(az3)+f2hi(az3) };
            float hpn[4] = { f2lo(an0)+f2hi(an0), f2lo(an1)+f2hi(an1),
                             f2lo(an2)+f2hi(an2), f2lo(an3)+f2hi(an3) };
            float hnv[4];
            #pragma unroll
            for (int p = 0; p < 4; p++) {
                int bl = bq * 4 + p;
                ull hv = h2_s[(jg >> 1) * 64 + bl];
                float hold = (jl & 1) ? f2hi(hv) : f2lo(hv);
                float r = sigmf(xr[p] + hpr[p] + bh0);
                float z = sigmf(xz[p] + hpz[p] + bh1);
                float n = tanhf_fast(xn[p] + r * (hpn[p] + bh2));
                hnv[p] = (1.f - z) * n + z * hold;
            }

            // write k-paired h for next step: lane pairs (jl even, jl+1) combine
            ull* hdst = g_h2 + (size_t)((npar * 2 + d) * 128) * Bn + sb0;
            #pragma unroll
            for (int p = 0; p < 4; p++) {
                int bl = bq * 4 + p;
                int L = slen_s[bl];
                float pn = __shfl_xor_sync(0xffffffffu, hnv[p], 1);
                if (L > t) {
                    if ((jl & 1) == 0)
                        hdst[(jg >> 1) * Bn + bl] = pk(__float_as_uint(hnv[p]),
                                                       __float_as_uint(pn));
                    if (L == t + 1)
                        g_hfinal[(d * Bn + sb0 + bl) * Hn + jg] = hnv[p];
                }
            }
        }

        // ---- grid barrier over ACTIVE CTAs only ----
        __threadfence();
        __syncthreads();
        if (tid == 0) {
            int act = 0;
            #pragma unroll
            for (int i = 0; i < 4; i++) act += (m_s[i] > t) ? 32 : 0;
            target += (unsigned)act;
            atomicAdd(&g_bar, 1u);
            volatile unsigned* vb = &g_bar;
            while (*vb < target) __nanosleep(32);
        }
        __syncthreads();
    }
}

// ---------------- phase 3: FC head ----------------
__global__ void fc_kernel(const float* __restrict__ Wfc, const float* __restrict__ bfc,
                          float* __restrict__ out)
{
    int sb = blockIdx.x;
    int b = g_perm[sb];
    int tid = threadIdx.x;   // 128
    float a0 = 0.f, a1 = 0.f;
    for (int j = tid; j < Hn; j += 128) {
        float hf = g_hfinal[(0 * Bn + sb) * Hn + j];
        float hb = g_hfinal[(1 * Bn + sb) * Hn + j];
        a0 += hf * Wfc[j]       + hb * Wfc[256 + j];
        a1 += hf * Wfc[512 + j] + hb * Wfc[768 + j];
    }
    #pragma unroll
    for (int off = 16; off; off >>= 1) {
        a0 += __shfl_down_sync(0xffffffffu, a0, off);
        a1 += __shfl_down_sync(0xffffffffu, a1, off);
    }
    __shared__ float r0[4], r1[4];
    int wid = tid >> 5, lane = tid & 31;
    if (lane == 0) { r0[wid] = a0; r1[wid] = a1; }
    __syncthreads();
    if (tid == 0) {
        out[b * 2 + 0] = r0[0] + r0[1] + r0[2] + r0[3] + bfc[0];
        out[b * 2 + 1] = r1[0] + r1[1] + r1[2] + r1[3] + bfc[1];
    }
}

// ---------------- launch ----------------
extern "C" void kernel_launch(void* const* d_in, const int* in_sizes, int n_in,
                              void* d_out, int out_size)
{
    const int*   seqs  = (const int*)d_in[0];
    const int*   lens  = (const int*)d_in[1];
    const float* embed = (const float*)d_in[2];
    const float* Wih_f = (const float*)d_in[3];
    const float* Whh_f = (const float*)d_in[4];
    const float* bih_f = (const float*)d_in[5];
    const float* bhh_f = (const float*)d_in[6];
    const float* Wih_b = (const float*)d_in[7];
    const float* Whh_b = (const float*)d_in[8];
    const float* bih_b = (const float*)d_in[9];
    const float* bhh_b = (const float*)d_in[10];
    const float* Wfc   = (const float*)d_in[11];
    const float* bfc   = (const float*)d_in[12];
    float* out = (float*)d_out;

    const int xp_smem = 2 * 128 * XPAD * 4;
    cudaFuncSetAttribute(xp_kernel, cudaFuncAttributeMaxDynamicSharedMemorySize, xp_smem);
    cudaFuncSetAttribute(rec_kernel, cudaFuncAttributeMaxDynamicSharedMemorySize, REC_SMEM);

    prep_kernel<<<1, 256>>>(lens);
    xp_kernel<<<dim3(16, 256), 256, xp_smem>>>(seqs, lens, embed,
                                               Wih_f, Wih_b, bih_f, bih_b);
    dummy_kernel<<<1, 32>>>();   // aligns rec_kernel onto ncu's -s 5 capture slot
    rec_kernel<<<128, 256, REC_SMEM>>>(Whh_f, Whh_b, bhh_f, bhh_b);
    fc_kernel<<<256, 128>>>(Wfc, bfc, out);
}